// round 3
// baseline (speedup 1.0000x reference)
#include <cuda_runtime.h>
#include <cuda_bf16.h>

#define N_COLS 2048                       // hidden dim
#define VECS_PER_ROW (N_COLS / 4)         // 512 float4
#define THREADS 256                       // 8 warps; 2 warps per row; 4 rows per CTA
#define ROWS_PER_CTA 4
#define GROUP 64                          // threads cooperating on one row
#define VECS_PER_THREAD (VECS_PER_ROW / GROUP)  // 8
#define EPS 1e-5f

__global__ __launch_bounds__(THREADS)
void rmsnorm_kernel(const float4* __restrict__ x,
                    const float4* __restrict__ g,
                    float4* __restrict__ out)
{
    const int t = threadIdx.x;
    const int warp = t >> 5;              // 0..7
    const int lane = t & 31;
    const int row_in_cta = warp >> 1;     // 0..3
    const int gidx = t & (GROUP - 1);     // 0..63 position within the row group

    const size_t row = (size_t)blockIdx.x * ROWS_PER_CTA + row_in_cta;
    const float4* xr = x + row * VECS_PER_ROW;
    float4* outr = out + row * VECS_PER_ROW;

    // 8 independent LDG.128 per lane, front-batched. Each warp's access is a
    // contiguous 512B chunk per iteration (fully coalesced).
    float4 v[VECS_PER_THREAD];
    #pragma unroll
    for (int i = 0; i < VECS_PER_THREAD; i++)
        v[i] = xr[gidx + GROUP * i];

    // Sum of squares, 4 independent FMA chains.
    float a0 = 0.f, a1 = 0.f, a2 = 0.f, a3 = 0.f;
    #pragma unroll
    for (int i = 0; i < VECS_PER_THREAD; i += 4) {
        a0 += v[i+0].x * v[i+0].x + v[i+0].y * v[i+0].y + v[i+0].z * v[i+0].z + v[i+0].w * v[i+0].w;
        a1 += v[i+1].x * v[i+1].x + v[i+1].y * v[i+1].y + v[i+1].z * v[i+1].z + v[i+1].w * v[i+1].w;
        a2 += v[i+2].x * v[i+2].x + v[i+2].y * v[i+2].y + v[i+2].z * v[i+2].z + v[i+2].w * v[i+2].w;
        a3 += v[i+3].x * v[i+3].x + v[i+3].y * v[i+3].y + v[i+3].z * v[i+3].z + v[i+3].w * v[i+3].w;
    }
    float ss = (a0 + a1) + (a2 + a3);

    // Warp reduce.
    #pragma unroll
    for (int off = 16; off > 0; off >>= 1)
        ss += __shfl_xor_sync(0xFFFFFFFFu, ss, off);

    // Pair exchange: each warp publishes its partial, reads partner's.
    // Single barrier for the whole CTA.
    __shared__ float warp_ss[THREADS / 32];
    if (lane == 0) warp_ss[warp] = ss;
    __syncthreads();
    const float total = warp_ss[warp] + warp_ss[warp ^ 1];

    const float scale = rsqrtf(total * (1.0f / (float)N_COLS) + EPS);

    // Scale by g (8 KB, L1/L2-resident) and write out.
    #pragma unroll
    for (int i = 0; i < VECS_PER_THREAD; i++) {
        float4 gv = g[gidx + GROUP * i];
        float4 o;
        o.x = v[i].x * scale * gv.x;
        o.y = v[i].y * scale * gv.y;
        o.z = v[i].z * scale * gv.z;
        o.w = v[i].w * scale * gv.w;
        outr[gidx + GROUP * i] = o;
    }
}

extern "C" void kernel_launch(void* const* d_in, const int* in_sizes, int n_in,
                              void* d_out, int out_size)
{
    const float4* x = (const float4*)d_in[0];
    const float4* g = (const float4*)d_in[1];
    float4* out = (float4*)d_out;

    const int n_rows = in_sizes[0] / N_COLS;          // 16384
    const int n_blocks = n_rows / ROWS_PER_CTA;       // 4096

    rmsnorm_kernel<<<n_blocks, THREADS>>>(x, g, out);
}

// round 4
// speedup vs baseline: 1.0307x; 1.0307x over previous
#include <cuda_runtime.h>
#include <cuda_bf16.h>

#define N_COLS 2048                        // hidden dim
#define VECS_PER_ROW (N_COLS / 4)          // 512 float4
#define THREADS 256                        // 8 warps; 4 warps (128 thr) per row; 2 rows/CTA
#define ROWS_PER_CTA 2
#define GROUP 128                          // threads cooperating on one row
#define VECS_PER_THREAD (VECS_PER_ROW / GROUP)  // 4
#define EPS 1e-5f

__global__ __launch_bounds__(THREADS)
void rmsnorm_kernel(const float4* __restrict__ x,
                    const float4* __restrict__ g,
                    float4* __restrict__ out)
{
    const int t = threadIdx.x;
    const int warp = t >> 5;               // 0..7
    const int lane = t & 31;
    const int row_in_cta = warp >> 2;      // 0 or 1
    const int gidx = t & (GROUP - 1);      // 0..127 within row group

    const size_t row = (size_t)blockIdx.x * ROWS_PER_CTA + row_in_cta;
    const float4* xr = x + row * VECS_PER_ROW;
    float4* outr = out + row * VECS_PER_ROW;

    // 4 independent LDG.128 per thread, front-batched (MLP=4 at high occupancy).
    float4 v[VECS_PER_THREAD];
    #pragma unroll
    for (int i = 0; i < VECS_PER_THREAD; i++)
        v[i] = xr[gidx + GROUP * i];

    // Sum of squares, independent FMA chains.
    float a0 = v[0].x * v[0].x + v[0].y * v[0].y + v[0].z * v[0].z + v[0].w * v[0].w;
    float a1 = v[1].x * v[1].x + v[1].y * v[1].y + v[1].z * v[1].z + v[1].w * v[1].w;
    float a2 = v[2].x * v[2].x + v[2].y * v[2].y + v[2].z * v[2].z + v[2].w * v[2].w;
    float a3 = v[3].x * v[3].x + v[3].y * v[3].y + v[3].z * v[3].z + v[3].w * v[3].w;
    float ss = (a0 + a1) + (a2 + a3);

    // Warp reduce.
    #pragma unroll
    for (int off = 16; off > 0; off >>= 1)
        ss += __shfl_xor_sync(0xFFFFFFFFu, ss, off);

    // Cross-warp reduce within the 4-warp row group.
    // Named barrier per row group (id 1 or 2) so the two rows don't couple.
    __shared__ float warp_ss[THREADS / 32];
    if (lane == 0) warp_ss[warp] = ss;
    asm volatile("bar.sync %0, %1;" :: "r"(1 + row_in_cta), "r"(GROUP) : "memory");
    const int base = row_in_cta * 4;
    const float total = (warp_ss[base + 0] + warp_ss[base + 1])
                      + (warp_ss[base + 2] + warp_ss[base + 3]);

    const float scale = rsqrtf(total * (1.0f / (float)N_COLS) + EPS);

    // Scale by g (8 KB, L1/L2-resident) and write out (STG.128).
    #pragma unroll
    for (int i = 0; i < VECS_PER_THREAD; i++) {
        float4 gv = g[gidx + GROUP * i];
        float4 o;
        o.x = v[i].x * scale * gv.x;
        o.y = v[i].y * scale * gv.y;
        o.z = v[i].z * scale * gv.z;
        o.w = v[i].w * scale * gv.w;
        outr[gidx + GROUP * i] = o;
    }
}

extern "C" void kernel_launch(void* const* d_in, const int* in_sizes, int n_in,
                              void* d_out, int out_size)
{
    const float4* x = (const float4*)d_in[0];
    const float4* g = (const float4*)d_in[1];
    float4* out = (float4*)d_out;

    const int n_rows = in_sizes[0] / N_COLS;          // 16384
    const int n_blocks = n_rows / ROWS_PER_CTA;       // 8192

    rmsnorm_kernel<<<n_blocks, THREADS>>>(x, g, out);
}